// round 12
// baseline (speedup 1.0000x reference)
#include <cuda_runtime.h>
#include <cuda_fp16.h>

// Pull_37091337568590, R12: R11 (fp16 channel-quad tiles, x-paired pixels,
// single barrier/stage, __stcs stores) + forced 3 blocks/SM (regs<=42,
// accepting minor spills) + __ldcg fill loads (L2-only, keep L1 for
// taps/spills).
// x: [8,16,512,512] f32, phi: [8,2,512,512] f32, out: [8,16,512,512] f32.

#define PB 8
#define PC 16
#define PH 512
#define PW 512
#define PHW (PH * PW)

#define TW 64
#define TH 32
#define HR 8
#define SW (TW + 2 * HR)       // 80 pixels per tile row
#define SH (TH + 2 * HR)       // 48 rows
#define SU 80                  // row stride in uint2
#define TILE_U2 (SH * SU)      // 3840 uint2 per buffer (30720 B)
#define NT 512
#define NRI 2                  // row iterations per thread (x2 px each)
#define NST 4                  // 4 channel-quad stages
#define FSLOTS (SH * (SW / 4)) // 960 float4 fill slots

__device__ __forceinline__ unsigned pk(float a, float b) {
    __half2 h = __floats2half2_rn(a, b);
    return *(unsigned*)&h;
}
__device__ __forceinline__ float2 up(unsigned u) {
    return __half22float2(*(__half2*)&u);
}

__global__ __launch_bounds__(NT, 3)
void pull_h4o_kernel(const float* __restrict__ x,
                     const float* __restrict__ phi,
                     float* __restrict__ out)
{
    extern __shared__ uint2 smemu[];
    uint2* bufA = smemu;
    uint2* bufB = smemu + TILE_U2;

    const int tx0 = blockIdx.x * TW;
    const int ty0 = blockIdx.y * TH;
    const int b   = blockIdx.z;
    const int tid = threadIdx.x;

    const int u  = tid & 31;         // x-pair index: pixels 2u, 2u+1
    const int py = tid >> 5;         // 0..15

    const float* __restrict__ phiy = phi + (size_t)b * 2 * PHW;
    const float* __restrict__ phix = phiy + PHW;
    const float* __restrict__ xb   = x   + (size_t)b * PC * PHW;
    float* __restrict__ ob         = out + (size_t)b * PC * PHW;

    // ---- per-pixel coords in registers: 2 row-iters x 2 px ----
    unsigned sel[NRI * 2];
    float    fwy[NRI * 2], fwx[NRI * 2];
    #pragma unroll
    for (int i = 0; i < NRI; i++) {
        int ly = py + i * 16;
        int h  = ty0 + ly;
        int wb = tx0 + 2 * u;
        int p  = h * PW + wb;

        float2 dy2 = __ldg((const float2*)(phiy + p));
        float2 dx2 = __ldg((const float2*)(phix + p));

        #pragma unroll
        for (int j = 0; j < 2; j++) {
            float cy = (j ? dy2.y : dy2.x) + (float)h;
            float cx = (j ? dx2.y : dx2.x) + (float)(wb + j);
            float y0f = floorf(cy);
            float x0f = floorf(cx);
            int k = i * 2 + j;
            fwy[k] = cy - y0f;
            fwx[k] = cx - x0f;

            int y0 = (int)y0f;
            int x0 = (int)x0f;
            int sy = y0 - (ty0 - HR);
            int sx = x0 - (tx0 - HR);

            if ((unsigned)sy < (SH - 1) && (unsigned)sx < (SW - 1)) {
                sel[k] = (unsigned)((sy * SU + sx) * 8);    // byte offset (uint2)
            } else {
                sel[k] = 0x80000000u | ((unsigned)(y0 & (PH - 1)) << 9)
                                     |  (unsigned)(x0 & (PW - 1));
            }
        }
    }

    // ---- fill mapping: 960 float4 slots, 2 passes ----
    const int slot0 = tid;
    const int slot1 = tid + NT;
    const bool act1 = (slot1 < FSLOTS);
    const int r0 = slot0 / 20, c40 = slot0 - r0 * 20;
    const int r1 = slot1 / 20, c41 = slot1 - r1 * 20;
    const int goff0 = (((ty0 - HR + r0) & (PH - 1)) * PW)
                    +  ((tx0 - HR + c40 * 4) & (PW - 1));
    const int goff1 = (((ty0 - HR + r1) & (PH - 1)) * PW)
                    +  ((tx0 - HR + c41 * 4) & (PW - 1));
    const int d0 = r0 * SU + c40 * 4;
    const int d1 = r1 * SU + c41 * 4;

    uint2 h0[4], h1[4];                      // packed fill regs (held one stage)

    auto fill_ldg = [&](int st) {
        const float* base = xb + (size_t)(4 * st) * PHW;
        {
            float4 a  = __ldcg((const float4*)(base + goff0));
            float4 bq = __ldcg((const float4*)(base + PHW + goff0));
            float4 c  = __ldcg((const float4*)(base + 2 * PHW + goff0));
            float4 d  = __ldcg((const float4*)(base + 3 * PHW + goff0));
            h0[0] = make_uint2(pk(a.x, bq.x), pk(c.x, d.x));
            h0[1] = make_uint2(pk(a.y, bq.y), pk(c.y, d.y));
            h0[2] = make_uint2(pk(a.z, bq.z), pk(c.z, d.z));
            h0[3] = make_uint2(pk(a.w, bq.w), pk(c.w, d.w));
        }
        if (act1) {
            float4 a  = __ldcg((const float4*)(base + goff1));
            float4 bq = __ldcg((const float4*)(base + PHW + goff1));
            float4 c  = __ldcg((const float4*)(base + 2 * PHW + goff1));
            float4 d  = __ldcg((const float4*)(base + 3 * PHW + goff1));
            h1[0] = make_uint2(pk(a.x, bq.x), pk(c.x, d.x));
            h1[1] = make_uint2(pk(a.y, bq.y), pk(c.y, d.y));
            h1[2] = make_uint2(pk(a.z, bq.z), pk(c.z, d.z));
            h1[3] = make_uint2(pk(a.w, bq.w), pk(c.w, d.w));
        }
    };
    auto fill_sts = [&](uint2* buf) {
        *(uint4*)(buf + d0)     = make_uint4(h0[0].x, h0[0].y, h0[1].x, h0[1].y);
        *(uint4*)(buf + d0 + 2) = make_uint4(h0[2].x, h0[2].y, h0[3].x, h0[3].y);
        if (act1) {
            *(uint4*)(buf + d1)     = make_uint4(h1[0].x, h1[0].y, h1[1].x, h1[1].y);
            *(uint4*)(buf + d1 + 2) = make_uint4(h1[2].x, h1[2].y, h1[3].x, h1[3].y);
        }
    };

    // ---- prologue: stage 0 staged, stage 1 LDG in flight ----
    fill_ldg(0);
    fill_sts(bufA);
    fill_ldg(1);
    __syncthreads();

    // ---- stage loop: ONE barrier per stage; fill(st+1) overlaps blend(st) --
    #pragma unroll
    for (int st = 0; st < NST; st++) {
        const uint2* __restrict__ cur = (st & 1) ? bufB : bufA;
        const float* __restrict__ c0 = xb + (size_t)(4 * st) * PHW;
        float* __restrict__ o0       = ob + (size_t)(4 * st) * PHW;

        if (st + 1 < NST) {
            fill_sts((st & 1) ? bufA : bufB);    // stage st+1
            if (st + 2 < NST) fill_ldg(st + 2);  // prefetch stage st+2
        }

        #pragma unroll
        for (int i = 0; i < NRI; i++) {
            float r[4][2];                       // [channel][px in pair]
            #pragma unroll
            for (int j = 0; j < 2; j++) {
                int k = i * 2 + j;
                unsigned sl = sel[k];
                float wy = fwy[k];
                float wx = fwx[k];

                float2 A00, A01, A10, A11;       // ch 0,1
                float2 B00, B01, B10, B11;       // ch 2,3
                if (!(sl & 0x80000000u)) {
                    const uint2* t = (const uint2*)((const char*)cur + sl);
                    uint2 v00 = t[0], v01 = t[1], v10 = t[SU], v11 = t[SU + 1];
                    A00 = up(v00.x); B00 = up(v00.y);
                    A01 = up(v01.x); B01 = up(v01.y);
                    A10 = up(v10.x); B10 = up(v10.y);
                    A11 = up(v11.x); B11 = up(v11.y);
                } else {
                    int y0 = (int)((sl >> 9) & (PH - 1));
                    int x0 = (int)(sl & (PW - 1));
                    int y1 = (y0 + 1) & (PH - 1);
                    int x1 = (x0 + 1) & (PW - 1);
                    int a = y0 * PW + x0, bq = y0 * PW + x1;
                    int cq = y1 * PW + x0, d = y1 * PW + x1;
                    A00 = make_float2(__ldg(c0 + a),            __ldg(c0 + PHW + a));
                    A01 = make_float2(__ldg(c0 + bq),           __ldg(c0 + PHW + bq));
                    A10 = make_float2(__ldg(c0 + cq),           __ldg(c0 + PHW + cq));
                    A11 = make_float2(__ldg(c0 + d),            __ldg(c0 + PHW + d));
                    B00 = make_float2(__ldg(c0 + 2 * PHW + a),  __ldg(c0 + 3 * PHW + a));
                    B01 = make_float2(__ldg(c0 + 2 * PHW + bq), __ldg(c0 + 3 * PHW + bq));
                    B10 = make_float2(__ldg(c0 + 2 * PHW + cq), __ldg(c0 + 3 * PHW + cq));
                    B11 = make_float2(__ldg(c0 + 2 * PHW + d),  __ldg(c0 + 3 * PHW + d));
                }

                float ta0 = A00.x + wx * (A01.x - A00.x);
                float ba0 = A10.x + wx * (A11.x - A10.x);
                float ta1 = A00.y + wx * (A01.y - A00.y);
                float ba1 = A10.y + wx * (A11.y - A10.y);
                float tb0 = B00.x + wx * (B01.x - B00.x);
                float bb0 = B10.x + wx * (B11.x - B10.x);
                float tb1 = B00.y + wx * (B01.y - B00.y);
                float bb1 = B10.y + wx * (B11.y - B10.y);

                r[0][j] = ta0 + wy * (ba0 - ta0);
                r[1][j] = ta1 + wy * (ba1 - ta1);
                r[2][j] = tb0 + wy * (bb0 - tb0);
                r[3][j] = tb1 + wy * (bb1 - tb1);
            }

            int prow = (ty0 + py + i * 16) * PW + tx0 + 2 * u;
            #pragma unroll
            for (int ch = 0; ch < 4; ch++)
                __stcs((float2*)(o0 + (size_t)ch * PHW + prow),
                       make_float2(r[ch][0], r[ch][1]));
        }

        if (st + 1 < NST)
            __syncthreads();   // fill(st+1) visible; readers of cur done
    }
}

extern "C" void kernel_launch(void* const* d_in, const int* in_sizes, int n_in,
                              void* d_out, int out_size)
{
    const float* x   = (const float*)d_in[0];
    const float* phi = (const float*)d_in[1];
    float* out = (float*)d_out;

    const int smem_bytes = 2 * TILE_U2 * sizeof(uint2);   // 61440 B
    static int configured = -1;
    if (configured < 0) {
        cudaFuncSetAttribute(pull_h4o_kernel,
                             cudaFuncAttributeMaxDynamicSharedMemorySize,
                             smem_bytes);
        configured = 1;
    }

    dim3 grid(PW / TW, PH / TH, PB);   // 8 x 16 x 8 = 1024 blocks
    pull_h4o_kernel<<<grid, NT, smem_bytes>>>(x, phi, out);
}

// round 13
// speedup vs baseline: 1.4293x; 1.4293x over previous
#include <cuda_runtime.h>
#include <cuda_fp16.h>

// Pull_37091337568590, R13: R11 structure restored (fp16 channel-quad tiles,
// x-paired pixels, single barrier/stage, held fill regs, 2 blocks/SM) +
// cache-policy hygiene: __ldcg fills (L2-only), __ldcs phi (streaming),
// __stcs outputs.
// x: [8,16,512,512] f32, phi: [8,2,512,512] f32, out: [8,16,512,512] f32.

#define PB 8
#define PC 16
#define PH 512
#define PW 512
#define PHW (PH * PW)

#define TW 64
#define TH 32
#define HR 8
#define SW (TW + 2 * HR)       // 80 pixels per tile row
#define SH (TH + 2 * HR)       // 48 rows
#define SU 80                  // row stride in uint2
#define TILE_U2 (SH * SU)      // 3840 uint2 per buffer (30720 B)
#define NT 512
#define NRI 2                  // row iterations per thread (x2 px each)
#define NST 4                  // 4 channel-quad stages
#define FSLOTS (SH * (SW / 4)) // 960 float4 fill slots

__device__ __forceinline__ unsigned pk(float a, float b) {
    __half2 h = __floats2half2_rn(a, b);
    return *(unsigned*)&h;
}
__device__ __forceinline__ float2 up(unsigned u) {
    return __half22float2(*(__half2*)&u);
}

__global__ __launch_bounds__(NT, 2)
void pull_h4r_kernel(const float* __restrict__ x,
                     const float* __restrict__ phi,
                     float* __restrict__ out)
{
    extern __shared__ uint2 smemu[];
    uint2* bufA = smemu;
    uint2* bufB = smemu + TILE_U2;

    const int tx0 = blockIdx.x * TW;
    const int ty0 = blockIdx.y * TH;
    const int b   = blockIdx.z;
    const int tid = threadIdx.x;

    const int u  = tid & 31;         // x-pair index: pixels 2u, 2u+1
    const int py = tid >> 5;         // 0..15

    const float* __restrict__ phiy = phi + (size_t)b * 2 * PHW;
    const float* __restrict__ phix = phiy + PHW;
    const float* __restrict__ xb   = x   + (size_t)b * PC * PHW;
    float* __restrict__ ob         = out + (size_t)b * PC * PHW;

    // ---- per-pixel coords in registers: 2 row-iters x 2 px ----
    unsigned sel[NRI * 2];
    float    fwy[NRI * 2], fwx[NRI * 2];
    #pragma unroll
    for (int i = 0; i < NRI; i++) {
        int ly = py + i * 16;
        int h  = ty0 + ly;
        int wb = tx0 + 2 * u;
        int p  = h * PW + wb;

        float2 dy2 = __ldcs((const float2*)(phiy + p));
        float2 dx2 = __ldcs((const float2*)(phix + p));

        #pragma unroll
        for (int j = 0; j < 2; j++) {
            float cy = (j ? dy2.y : dy2.x) + (float)h;
            float cx = (j ? dx2.y : dx2.x) + (float)(wb + j);
            float y0f = floorf(cy);
            float x0f = floorf(cx);
            int k = i * 2 + j;
            fwy[k] = cy - y0f;
            fwx[k] = cx - x0f;

            int y0 = (int)y0f;
            int x0 = (int)x0f;
            int sy = y0 - (ty0 - HR);
            int sx = x0 - (tx0 - HR);

            if ((unsigned)sy < (SH - 1) && (unsigned)sx < (SW - 1)) {
                sel[k] = (unsigned)((sy * SU + sx) * 8);    // byte offset (uint2)
            } else {
                sel[k] = 0x80000000u | ((unsigned)(y0 & (PH - 1)) << 9)
                                     |  (unsigned)(x0 & (PW - 1));
            }
        }
    }

    // ---- fill mapping: 960 float4 slots, 2 passes ----
    const int slot0 = tid;
    const int slot1 = tid + NT;
    const bool act1 = (slot1 < FSLOTS);
    const int r0 = slot0 / 20, c40 = slot0 - r0 * 20;
    const int r1 = slot1 / 20, c41 = slot1 - r1 * 20;
    const int goff0 = (((ty0 - HR + r0) & (PH - 1)) * PW)
                    +  ((tx0 - HR + c40 * 4) & (PW - 1));
    const int goff1 = (((ty0 - HR + r1) & (PH - 1)) * PW)
                    +  ((tx0 - HR + c41 * 4) & (PW - 1));
    const int d0 = r0 * SU + c40 * 4;
    const int d1 = r1 * SU + c41 * 4;

    uint2 h0[4], h1[4];                      // packed fill regs (held one stage)

    auto fill_ldg = [&](int st) {
        const float* base = xb + (size_t)(4 * st) * PHW;
        {
            float4 a  = __ldcg((const float4*)(base + goff0));
            float4 bq = __ldcg((const float4*)(base + PHW + goff0));
            float4 c  = __ldcg((const float4*)(base + 2 * PHW + goff0));
            float4 d  = __ldcg((const float4*)(base + 3 * PHW + goff0));
            h0[0] = make_uint2(pk(a.x, bq.x), pk(c.x, d.x));
            h0[1] = make_uint2(pk(a.y, bq.y), pk(c.y, d.y));
            h0[2] = make_uint2(pk(a.z, bq.z), pk(c.z, d.z));
            h0[3] = make_uint2(pk(a.w, bq.w), pk(c.w, d.w));
        }
        if (act1) {
            float4 a  = __ldcg((const float4*)(base + goff1));
            float4 bq = __ldcg((const float4*)(base + PHW + goff1));
            float4 c  = __ldcg((const float4*)(base + 2 * PHW + goff1));
            float4 d  = __ldcg((const float4*)(base + 3 * PHW + goff1));
            h1[0] = make_uint2(pk(a.x, bq.x), pk(c.x, d.x));
            h1[1] = make_uint2(pk(a.y, bq.y), pk(c.y, d.y));
            h1[2] = make_uint2(pk(a.z, bq.z), pk(c.z, d.z));
            h1[3] = make_uint2(pk(a.w, bq.w), pk(c.w, d.w));
        }
    };
    auto fill_sts = [&](uint2* buf) {
        *(uint4*)(buf + d0)     = make_uint4(h0[0].x, h0[0].y, h0[1].x, h0[1].y);
        *(uint4*)(buf + d0 + 2) = make_uint4(h0[2].x, h0[2].y, h0[3].x, h0[3].y);
        if (act1) {
            *(uint4*)(buf + d1)     = make_uint4(h1[0].x, h1[0].y, h1[1].x, h1[1].y);
            *(uint4*)(buf + d1 + 2) = make_uint4(h1[2].x, h1[2].y, h1[3].x, h1[3].y);
        }
    };

    // ---- prologue: stage 0 staged, stage 1 LDG in flight ----
    fill_ldg(0);
    fill_sts(bufA);
    fill_ldg(1);
    __syncthreads();

    // ---- stage loop: ONE barrier per stage; fill(st+1) overlaps blend(st) --
    #pragma unroll
    for (int st = 0; st < NST; st++) {
        const uint2* __restrict__ cur = (st & 1) ? bufB : bufA;
        const float* __restrict__ c0 = xb + (size_t)(4 * st) * PHW;
        float* __restrict__ o0       = ob + (size_t)(4 * st) * PHW;

        if (st + 1 < NST) {
            fill_sts((st & 1) ? bufA : bufB);    // stage st+1
            if (st + 2 < NST) fill_ldg(st + 2);  // prefetch stage st+2
        }

        #pragma unroll
        for (int i = 0; i < NRI; i++) {
            float r[4][2];                       // [channel][px in pair]
            #pragma unroll
            for (int j = 0; j < 2; j++) {
                int k = i * 2 + j;
                unsigned sl = sel[k];
                float wy = fwy[k];
                float wx = fwx[k];

                float2 A00, A01, A10, A11;       // ch 0,1
                float2 B00, B01, B10, B11;       // ch 2,3
                if (!(sl & 0x80000000u)) {
                    const uint2* t = (const uint2*)((const char*)cur + sl);
                    uint2 v00 = t[0], v01 = t[1], v10 = t[SU], v11 = t[SU + 1];
                    A00 = up(v00.x); B00 = up(v00.y);
                    A01 = up(v01.x); B01 = up(v01.y);
                    A10 = up(v10.x); B10 = up(v10.y);
                    A11 = up(v11.x); B11 = up(v11.y);
                } else {
                    int y0 = (int)((sl >> 9) & (PH - 1));
                    int x0 = (int)(sl & (PW - 1));
                    int y1 = (y0 + 1) & (PH - 1);
                    int x1 = (x0 + 1) & (PW - 1);
                    int a = y0 * PW + x0, bq = y0 * PW + x1;
                    int cq = y1 * PW + x0, d = y1 * PW + x1;
                    A00 = make_float2(__ldg(c0 + a),            __ldg(c0 + PHW + a));
                    A01 = make_float2(__ldg(c0 + bq),           __ldg(c0 + PHW + bq));
                    A10 = make_float2(__ldg(c0 + cq),           __ldg(c0 + PHW + cq));
                    A11 = make_float2(__ldg(c0 + d),            __ldg(c0 + PHW + d));
                    B00 = make_float2(__ldg(c0 + 2 * PHW + a),  __ldg(c0 + 3 * PHW + a));
                    B01 = make_float2(__ldg(c0 + 2 * PHW + bq), __ldg(c0 + 3 * PHW + bq));
                    B10 = make_float2(__ldg(c0 + 2 * PHW + cq), __ldg(c0 + 3 * PHW + cq));
                    B11 = make_float2(__ldg(c0 + 2 * PHW + d),  __ldg(c0 + 3 * PHW + d));
                }

                float ta0 = A00.x + wx * (A01.x - A00.x);
                float ba0 = A10.x + wx * (A11.x - A10.x);
                float ta1 = A00.y + wx * (A01.y - A00.y);
                float ba1 = A10.y + wx * (A11.y - A10.y);
                float tb0 = B00.x + wx * (B01.x - B00.x);
                float bb0 = B10.x + wx * (B11.x - B10.x);
                float tb1 = B00.y + wx * (B01.y - B00.y);
                float bb1 = B10.y + wx * (B11.y - B10.y);

                r[0][j] = ta0 + wy * (ba0 - ta0);
                r[1][j] = ta1 + wy * (ba1 - ta1);
                r[2][j] = tb0 + wy * (bb0 - tb0);
                r[3][j] = tb1 + wy * (bb1 - tb1);
            }

            int prow = (ty0 + py + i * 16) * PW + tx0 + 2 * u;
            #pragma unroll
            for (int ch = 0; ch < 4; ch++)
                __stcs((float2*)(o0 + (size_t)ch * PHW + prow),
                       make_float2(r[ch][0], r[ch][1]));
        }

        if (st + 1 < NST)
            __syncthreads();   // fill(st+1) visible; readers of cur done
    }
}

extern "C" void kernel_launch(void* const* d_in, const int* in_sizes, int n_in,
                              void* d_out, int out_size)
{
    const float* x   = (const float*)d_in[0];
    const float* phi = (const float*)d_in[1];
    float* out = (float*)d_out;

    const int smem_bytes = 2 * TILE_U2 * sizeof(uint2);   // 61440 B
    static int configured = -1;
    if (configured < 0) {
        cudaFuncSetAttribute(pull_h4r_kernel,
                             cudaFuncAttributeMaxDynamicSharedMemorySize,
                             smem_bytes);
        configured = 1;
    }

    dim3 grid(PW / TW, PH / TH, PB);   // 8 x 16 x 8 = 1024 blocks
    pull_h4r_kernel<<<grid, NT, smem_bytes>>>(x, phi, out);
}